// round 6
// baseline (speedup 1.0000x reference)
#include <cuda_runtime.h>
#include <cuda_bf16.h>
#include <cstdint>

// ============================================================================
// TernaryLinear: out[8192,4096] = x[8192,4096] @ W[4096,4096]^T + bias
//
// R6: warp-specialized dual-pipe.
//   warps 0-3: pure IMMA (hi pass), one per SMSP, warp tile 32x64.
//   warps 4-7: pure dp4a (lo pass), one per SMSP, warp tile 16x128.
// Tensor and fma pipes are fed by different warps on each SMSP -> natural
// overlap via the issue arbiter, no phase alignment needed.
// out = s_row * (256*(H@W^T) + (L@W^T)) + bias, all-int accumulation (exact).
// ============================================================================

#define M_DIM 8192
#define N_DIM 4096
#define K_DIM 4096
#define BM 64
#define BN 128
#define BK 128                     // int8 elems per K tile (128 B/row)
#define NKT (K_DIM / BK)           // 32
#define NSTAGE 4
#define A_HI_OFF 0
#define A_LO_OFF 8192
#define B_OFF    16384
#define STAGE_BYTES 32768          // A_hi 8K + A_lo 8K + B 16K
#define SMEM_TOTAL (NSTAGE * STAGE_BYTES)   // 128 KB

// Static device scratch (sanctioned workaround for no-alloc rule)
__device__ __align__(128) int8_t g_xh8[(size_t)M_DIM * K_DIM];
__device__ __align__(128) int8_t g_xl8[(size_t)M_DIM * K_DIM];
__device__ __align__(128) int8_t g_w8 [(size_t)N_DIM * K_DIM];
__device__ __align__(128) float  g_scale[M_DIM];

// ---------------------------------------------------------------------------
// PTX helpers
// ---------------------------------------------------------------------------
__device__ __forceinline__ uint32_t smem_u32(const void* p) {
    uint32_t a;
    asm("{ .reg .u64 t; cvta.to.shared.u64 t, %1; cvt.u32.u64 %0, t; }"
        : "=r"(a) : "l"(p));
    return a;
}

#define CP16(dst, src) \
    asm volatile("cp.async.cg.shared.global [%0], [%1], 16;" \
                 :: "r"((uint32_t)(dst)), "l"(src) : "memory")
#define CP_COMMIT() asm volatile("cp.async.commit_group;" ::: "memory")
#define CP_WAIT1()  asm volatile("cp.async.wait_group 1;" ::: "memory")

#define LDSM4(r0, r1, r2, r3, addr) \
    asm volatile("ldmatrix.sync.aligned.m8n8.x4.shared.b16 {%0,%1,%2,%3}, [%4];" \
                 : "=r"(r0), "=r"(r1), "=r"(r2), "=r"(r3) : "r"(addr))

__device__ __forceinline__ void mma_s8(int c[4], const uint32_t a[4],
                                       uint32_t b0, uint32_t b1) {
    asm volatile(
        "mma.sync.aligned.m16n8k32.row.col.s32.s8.s8.s32 "
        "{%0,%1,%2,%3}, {%4,%5,%6,%7}, {%8,%9}, {%0,%1,%2,%3};"
        : "+r"(c[0]), "+r"(c[1]), "+r"(c[2]), "+r"(c[3])
        : "r"(a[0]), "r"(a[1]), "r"(a[2]), "r"(a[3]), "r"(b0), "r"(b1));
}

// ---------------------------------------------------------------------------
// Merged pre-pass: blocks [0,8192) quantize x rows; [8192, 24576) convert W.
// ---------------------------------------------------------------------------
__global__ void __launch_bounds__(256) quant_all_kernel(const float* __restrict__ x,
                                                        const float* __restrict__ w) {
    const int t = threadIdx.x;
    if (blockIdx.x < M_DIM) {
        const int row = blockIdx.x;
        const float4* xr = reinterpret_cast<const float4*>(x + (size_t)row * K_DIM);
        float4 v[4];
        float amax = 0.f;
#pragma unroll
        for (int p = 0; p < 4; ++p) {
            v[p] = xr[p * 256 + t];
            amax = fmaxf(amax, fmaxf(fmaxf(fabsf(v[p].x), fabsf(v[p].y)),
                                     fmaxf(fabsf(v[p].z), fabsf(v[p].w))));
        }
#pragma unroll
        for (int o = 16; o; o >>= 1)
            amax = fmaxf(amax, __shfl_xor_sync(0xFFFFFFFFu, amax, o));

        __shared__ float smax[8];
        if ((t & 31) == 0) smax[t >> 5] = amax;
        __syncthreads();
        float bmax = fmaxf(fmaxf(fmaxf(smax[0], smax[1]), fmaxf(smax[2], smax[3])),
                           fmaxf(fmaxf(smax[4], smax[5]), fmaxf(smax[6], smax[7])));

        const float inv = (bmax > 0.f) ? (32639.f / bmax) : 0.f;
        if (t == 0) g_scale[row] = (bmax > 0.f) ? (bmax / 32639.f) : 0.f;

        char4* hp = reinterpret_cast<char4*>(g_xh8 + (size_t)row * K_DIM);
        char4* lp = reinterpret_cast<char4*>(g_xl8 + (size_t)row * K_DIM);
#pragma unroll
        for (int p = 0; p < 4; ++p) {
            int q0 = __float2int_rn(v[p].x * inv);
            int q1 = __float2int_rn(v[p].y * inv);
            int q2 = __float2int_rn(v[p].z * inv);
            int q3 = __float2int_rn(v[p].w * inv);
            int h0 = (q0 + 128) >> 8, h1 = (q1 + 128) >> 8;
            int h2 = (q2 + 128) >> 8, h3 = (q3 + 128) >> 8;
            char4 hc = make_char4((char)h0, (char)h1, (char)h2, (char)h3);
            char4 lc = make_char4((char)(q0 - (h0 << 8)), (char)(q1 - (h1 << 8)),
                                  (char)(q2 - (h2 << 8)), (char)(q3 - (h3 << 8)));
            hp[p * 256 + t] = hc;
            lp[p * 256 + t] = lc;
        }
    } else {
        size_t i = (size_t)(blockIdx.x - M_DIM) * 256 + t;   // float4 index
        float4 v = reinterpret_cast<const float4*>(w)[i];
        char4 c = make_char4((char)__float2int_rn(v.x), (char)__float2int_rn(v.y),
                             (char)__float2int_rn(v.z), (char)__float2int_rn(v.w));
        reinterpret_cast<char4*>(g_w8)[i] = c;
    }
}

// ---------------------------------------------------------------------------
// Main warp-specialized GEMM. CTA 64x128, 256 thr = 8 warps.
//   warps 0-3 (tensor): wm = wid&1, wn2 = wid>>1; warp tile 32(m) x 64(n),
//       accH[2][8][4] int32, 64 IMMA per iter.
//   warps 4-7 (dp4a): w = wid-4; rows w*16..w*16+15, cols lane+32j;
//       accLo[16][4], 2048 dp4a per iter.
// 4-stage cp.async ring, prefetch distance 2, one __syncthreads per iter.
// ---------------------------------------------------------------------------
__global__ void __launch_bounds__(256, 1)
gemm_s8_kernel(const float* __restrict__ bias, float* __restrict__ out) {
    extern __shared__ char smem[];
    const uint32_t sb = smem_u32(smem);
    const int tid = threadIdx.x;
    const int lane = tid & 31;
    const int wid = tid >> 5;
    const int m0 = blockIdx.y * BM;
    const int n0 = blockIdx.x * BN;

    // --- cp.async mapping (8 x 16B chunks per thread = 32 KB/stage) ---
    const int arow = tid >> 2;
    const int acol = (tid & 3) * 2;
    const int8_t* gH = g_xh8 + (size_t)(m0 + arow) * K_DIM + acol * 16;
    const int8_t* gL = g_xl8 + (size_t)(m0 + arow) * K_DIM + acol * 16;
    const uint32_t aBase = (uint32_t)arow * BK;
    const uint32_t asw0 = aBase + (uint32_t)(((acol + 0) ^ (arow & 7)) << 4);
    const uint32_t asw1 = aBase + (uint32_t)(((acol + 1) ^ (arow & 7)) << 4);
    const int brow = tid >> 1;
    const int bcol = (tid & 1) * 4;
    const int8_t* gW = g_w8 + (size_t)(n0 + brow) * K_DIM + bcol * 16;
    const uint32_t bBase = B_OFF + (uint32_t)brow * BK;
    uint32_t bsw[4];
#pragma unroll
    for (int j = 0; j < 4; ++j)
        bsw[j] = bBase + (uint32_t)(((bcol + j) ^ (brow & 7)) << 4);

#define PREFETCH(it) do {                                                     \
    const int _k = (it) * BK;                                                 \
    const uint32_t _s = sb + (uint32_t)((it) & (NSTAGE - 1)) * STAGE_BYTES;   \
    CP16(_s + A_HI_OFF + asw0, gH + _k);                                      \
    CP16(_s + A_HI_OFF + asw1, gH + _k + 16);                                 \
    CP16(_s + A_LO_OFF + asw0, gL + _k);                                      \
    CP16(_s + A_LO_OFF + asw1, gL + _k + 16);                                 \
    CP16(_s + bsw[0], gW + _k);                                               \
    CP16(_s + bsw[1], gW + _k + 16);                                          \
    CP16(_s + bsw[2], gW + _k + 32);                                          \
    CP16(_s + bsw[3], gW + _k + 48);                                          \
} while (0)

    // --- prologue: fill 2 stages (prefetch distance 2) ---
    PREFETCH(0); CP_COMMIT();
    PREFETCH(1); CP_COMMIT();

    if (wid < 4) {
        // ===================== TENSOR WARPS (hi pass) =====================
        const int wm = wid & 1;         // m half (32 rows)
        const int wn2 = wid >> 1;       // n half (64 cols)

        const int ag = lane >> 3;
        const int aRow0 = wm * 32 + ((ag & 1) << 3) + (lane & 7);
        const int agc = ag >> 1;
        const int bR = wn2 * 64 + lane;           // group 0 rows; group 1 = +32
        const uint32_t bOff0 = B_OFF + (uint32_t)bR * BK;
        const uint32_t bOff1 = B_OFF + (uint32_t)(bR + 32) * BK;
        const int bSw = lane & 7;                 // (row&7) same for both groups

        int accH[2][8][4];
#pragma unroll
        for (int mt = 0; mt < 2; ++mt)
#pragma unroll
            for (int nt = 0; nt < 8; ++nt)
#pragma unroll
                for (int i = 0; i < 4; ++i) accH[mt][nt][i] = 0;

        for (int it = 0; it < NKT; ++it) {
            CP_WAIT1();
            __syncthreads();
            if (it + 2 < NKT) { PREFETCH(it + 2); }
            CP_COMMIT();

            const uint32_t S = sb + (uint32_t)(it & (NSTAGE - 1)) * STAGE_BYTES;
#pragma unroll
            for (int ks = 0; ks < 4; ++ks) {
                uint32_t b0[2][4], b1[2][4];
                {
                    const uint32_t c0 = (uint32_t)(((ks * 2)     ^ bSw) << 4);
                    const uint32_t c1 = (uint32_t)(((ks * 2 + 1) ^ bSw) << 4);
                    LDSM4(b0[0][0], b0[0][1], b0[0][2], b0[0][3], S + bOff0 + c0);
                    LDSM4(b1[0][0], b1[0][1], b1[0][2], b1[0][3], S + bOff0 + c1);
                    LDSM4(b0[1][0], b0[1][1], b0[1][2], b0[1][3], S + bOff1 + c0);
                    LDSM4(b1[1][0], b1[1][1], b1[1][2], b1[1][3], S + bOff1 + c1);
                }
                uint32_t ah[2][4];
#pragma unroll
                for (int mt = 0; mt < 2; ++mt) {
                    const int rA = aRow0 + mt * 16;
                    const int cA = ks * 2 + agc;
                    const uint32_t off = (uint32_t)rA * BK +
                                         (uint32_t)((cA ^ (rA & 7)) << 4);
                    LDSM4(ah[mt][0], ah[mt][1], ah[mt][2], ah[mt][3],
                          S + A_HI_OFF + off);
                }
#pragma unroll
                for (int mt = 0; mt < 2; ++mt)
#pragma unroll
                    for (int nt = 0; nt < 8; ++nt)
                        mma_s8(accH[mt][nt], ah[mt],
                               b0[nt >> 2][nt & 3], b1[nt >> 2][nt & 3]);
            }
        }

        // wait for dp4a warps to finish + stage their accumulators
        __syncthreads();   // (1) all mainloop smem reads done
        __syncthreads();   // (2) loS written by dp4a warps
        const int* loS = reinterpret_cast<const int*>(smem);

        // epilogue: combine hi/lo, scale, bias, store fp32
#pragma unroll
        for (int mt = 0; mt < 2; ++mt) {
            const int rl = wm * 32 + mt * 16 + (lane >> 2);
            const int r0 = m0 + rl;
            const float s0 = g_scale[r0];
            const float s1 = g_scale[r0 + 8];
#pragma unroll
            for (int nt = 0; nt < 8; ++nt) {
                const int cl = wn2 * 64 + nt * 8 + 2 * (lane & 3);
                const int col = n0 + cl;
                const float bv0 = __ldg(bias + col);
                const float bv1 = __ldg(bias + col + 1);
                const int* h = accH[mt][nt];
                float2 o0, o1;
                o0.x = s0 * (float)(256 * h[0] + loS[rl * BN + cl])           + bv0;
                o0.y = s0 * (float)(256 * h[1] + loS[rl * BN + cl + 1])       + bv1;
                o1.x = s1 * (float)(256 * h[2] + loS[(rl + 8) * BN + cl])     + bv0;
                o1.y = s1 * (float)(256 * h[3] + loS[(rl + 8) * BN + cl + 1]) + bv1;
                *reinterpret_cast<float2*>(out + (size_t)r0 * N_DIM + col) = o0;
                *reinterpret_cast<float2*>(out + (size_t)(r0 + 8) * N_DIM + col) = o1;
            }
        }
    } else {
        // ====================== DP4A WARPS (lo pass) ======================
        const int w = wid - 4;          // 0..3 -> rows w*16 .. w*16+15
        int accLo[16][4];
#pragma unroll
        for (int i = 0; i < 16; ++i)
#pragma unroll
            for (int j = 0; j < 4; ++j) accLo[i][j] = 0;

        uint32_t loB[4];
#pragma unroll
        for (int j = 0; j < 4; ++j)
            loB[j] = B_OFF + (uint32_t)(lane + 32 * j) * BK;
        const int loBSw = lane & 7;
        const uint32_t loA = A_LO_OFF + (uint32_t)(w * 16) * BK;

        for (int it = 0; it < NKT; ++it) {
            CP_WAIT1();
            __syncthreads();
            if (it + 2 < NKT) { PREFETCH(it + 2); }
            CP_COMMIT();

            const uint32_t So = (uint32_t)(it & (NSTAGE - 1)) * STAGE_BYTES;
#pragma unroll
            for (int kc = 0; kc < 8; ++kc) {
                uint4 bw[4];
#pragma unroll
                for (int j = 0; j < 4; ++j)
                    bw[j] = *reinterpret_cast<const uint4*>(
                        smem + So + loB[j] + ((kc ^ loBSw) << 4));
#pragma unroll
                for (int i = 0; i < 16; ++i) {
                    const uint4 aw = *reinterpret_cast<const uint4*>(
                        smem + So + loA + (uint32_t)i * BK + ((kc ^ (i & 7)) << 4));
#pragma unroll
                    for (int j = 0; j < 4; ++j) {
                        int acc = accLo[i][j];
                        acc = __dp4a((int)aw.x, (int)bw[j].x, acc);
                        acc = __dp4a((int)aw.y, (int)bw[j].y, acc);
                        acc = __dp4a((int)aw.z, (int)bw[j].z, acc);
                        acc = __dp4a((int)aw.w, (int)bw[j].w, acc);
                        accLo[i][j] = acc;
                    }
                }
            }
        }

        // stage lo accumulators to smem (64 x 128 int32 = 32 KB)
        __syncthreads();   // (1) all mainloop smem reads done (both groups)
        int* loS = reinterpret_cast<int*>(smem);
#pragma unroll
        for (int i = 0; i < 16; ++i)
#pragma unroll
            for (int j = 0; j < 4; ++j)
                loS[(w * 16 + i) * BN + lane + 32 * j] = accLo[i][j];
        __syncthreads();   // (2) publish loS to tensor warps
    }
#undef PREFETCH
}

// ---------------------------------------------------------------------------
// Launch
// ---------------------------------------------------------------------------
extern "C" void kernel_launch(void* const* d_in, const int* in_sizes, int n_in,
                              void* d_out, int out_size) {
    const float* x    = (const float*)d_in[0];
    const float* w    = (const float*)d_in[1];
    const float* bias = (const float*)d_in[2];
    float* out = (float*)d_out;

    quant_all_kernel<<<M_DIM + (N_DIM * K_DIM / 4) / 256, 256>>>(x, w);

    cudaFuncSetAttribute(gemm_s8_kernel,
                         cudaFuncAttributeMaxDynamicSharedMemorySize, SMEM_TOTAL);
    dim3 grid(N_DIM / BN, M_DIM / BM);   // (32, 128): n fastest -> W L2-resident
    gemm_s8_kernel<<<grid, 256, SMEM_TOTAL>>>(bias, out);
}

// round 7
// speedup vs baseline: 1.4339x; 1.4339x over previous
#include <cuda_runtime.h>
#include <cuda_bf16.h>
#include <cstdint>

// ============================================================================
// TernaryLinear: out[8192,4096] = x[8192,4096] @ W[4096,4096]^T + bias
//
// R7: balanced dual-pipe, fine interleave.
// Machine model (fit from R2-R6): fallback IMMA = 64 MAC/cyc/SMSP,
// dp4a = 128 MAC/cyc/SMSP (rt~1). So dp4a carries MORE work:
//   tensor: hi pass, ks 0..2   (24 mma/warp/iter, 3072 cyc/SMSP)
//   dp4a:   lo pass ks 0..3  + hi pass ks 3 (1280 dp4a/warp, ~2560 cyc/SMSP)
// Interleaved [2 mma | 64 dp4a] so the shallow tensor queue never freezes a
// warp. out = s*(256*(hi_mma+hi_dp) + lo) + bias, all-int accumulation.
// ============================================================================

#define M_DIM 8192
#define N_DIM 4096
#define K_DIM 4096
#define BM 64
#define BN 128
#define BK 128                     // int8 elems per K tile (128 B/row)
#define NKT (K_DIM / BK)           // 32
#define NSTAGE 4
#define A_HI_OFF 0
#define A_LO_OFF 8192
#define B_OFF    16384
#define STAGE_BYTES 32768          // A_hi 8K + A_lo 8K + B 16K
#define SMEM_TOTAL (NSTAGE * STAGE_BYTES)   // 128 KB

// Static device scratch (sanctioned workaround for no-alloc rule)
__device__ __align__(128) int8_t g_xh8[(size_t)M_DIM * K_DIM];
__device__ __align__(128) int8_t g_xl8[(size_t)M_DIM * K_DIM];
__device__ __align__(128) int8_t g_w8 [(size_t)N_DIM * K_DIM];
__device__ __align__(128) float  g_scale[M_DIM];

// ---------------------------------------------------------------------------
// PTX helpers
// ---------------------------------------------------------------------------
__device__ __forceinline__ uint32_t smem_u32(const void* p) {
    uint32_t a;
    asm("{ .reg .u64 t; cvta.to.shared.u64 t, %1; cvt.u32.u64 %0, t; }"
        : "=r"(a) : "l"(p));
    return a;
}

#define CP16(dst, src) \
    asm volatile("cp.async.cg.shared.global [%0], [%1], 16;" \
                 :: "r"((uint32_t)(dst)), "l"(src) : "memory")
#define CP_COMMIT() asm volatile("cp.async.commit_group;" ::: "memory")
#define CP_WAIT1()  asm volatile("cp.async.wait_group 1;" ::: "memory")

#define LDSM4(r0, r1, r2, r3, addr) \
    asm volatile("ldmatrix.sync.aligned.m8n8.x4.shared.b16 {%0,%1,%2,%3}, [%4];" \
                 : "=r"(r0), "=r"(r1), "=r"(r2), "=r"(r3) : "r"(addr))

__device__ __forceinline__ void mma_s8(int c[4], const uint32_t a[4],
                                       uint32_t b0, uint32_t b1) {
    asm volatile(
        "mma.sync.aligned.m16n8k32.row.col.s32.s8.s8.s32 "
        "{%0,%1,%2,%3}, {%4,%5,%6,%7}, {%8,%9}, {%0,%1,%2,%3};"
        : "+r"(c[0]), "+r"(c[1]), "+r"(c[2]), "+r"(c[3])
        : "r"(a[0]), "r"(a[1]), "r"(a[2]), "r"(a[3]), "r"(b0), "r"(b1));
}

// ---------------------------------------------------------------------------
// Merged pre-pass: blocks [0,8192) quantize x rows; [8192, 24576) convert W.
// ---------------------------------------------------------------------------
__global__ void __launch_bounds__(256) quant_all_kernel(const float* __restrict__ x,
                                                        const float* __restrict__ w) {
    const int t = threadIdx.x;
    if (blockIdx.x < M_DIM) {
        const int row = blockIdx.x;
        const float4* xr = reinterpret_cast<const float4*>(x + (size_t)row * K_DIM);
        float4 v[4];
        float amax = 0.f;
#pragma unroll
        for (int p = 0; p < 4; ++p) {
            v[p] = xr[p * 256 + t];
            amax = fmaxf(amax, fmaxf(fmaxf(fabsf(v[p].x), fabsf(v[p].y)),
                                     fmaxf(fabsf(v[p].z), fabsf(v[p].w))));
        }
#pragma unroll
        for (int o = 16; o; o >>= 1)
            amax = fmaxf(amax, __shfl_xor_sync(0xFFFFFFFFu, amax, o));

        __shared__ float smax[8];
        if ((t & 31) == 0) smax[t >> 5] = amax;
        __syncthreads();
        float bmax = fmaxf(fmaxf(fmaxf(smax[0], smax[1]), fmaxf(smax[2], smax[3])),
                           fmaxf(fmaxf(smax[4], smax[5]), fmaxf(smax[6], smax[7])));

        const float inv = (bmax > 0.f) ? (32639.f / bmax) : 0.f;
        if (t == 0) g_scale[row] = (bmax > 0.f) ? (bmax / 32639.f) : 0.f;

        char4* hp = reinterpret_cast<char4*>(g_xh8 + (size_t)row * K_DIM);
        char4* lp = reinterpret_cast<char4*>(g_xl8 + (size_t)row * K_DIM);
#pragma unroll
        for (int p = 0; p < 4; ++p) {
            int q0 = __float2int_rn(v[p].x * inv);
            int q1 = __float2int_rn(v[p].y * inv);
            int q2 = __float2int_rn(v[p].z * inv);
            int q3 = __float2int_rn(v[p].w * inv);
            int h0 = (q0 + 128) >> 8, h1 = (q1 + 128) >> 8;
            int h2 = (q2 + 128) >> 8, h3 = (q3 + 128) >> 8;
            char4 hc = make_char4((char)h0, (char)h1, (char)h2, (char)h3);
            char4 lc = make_char4((char)(q0 - (h0 << 8)), (char)(q1 - (h1 << 8)),
                                  (char)(q2 - (h2 << 8)), (char)(q3 - (h3 << 8)));
            hp[p * 256 + t] = hc;
            lp[p * 256 + t] = lc;
        }
    } else {
        size_t i = (size_t)(blockIdx.x - M_DIM) * 256 + t;   // float4 index
        float4 v = reinterpret_cast<const float4*>(w)[i];
        char4 c = make_char4((char)__float2int_rn(v.x), (char)__float2int_rn(v.y),
                             (char)__float2int_rn(v.z), (char)__float2int_rn(v.w));
        reinterpret_cast<char4*>(g_w8)[i] = c;
    }
}

// ---------------------------------------------------------------------------
// Main balanced GEMM. CTA 64x128, 256 thr = 8 warps (2m x 4n hi-tiles 32x32).
//   tensor: accH[2][4][4], 8 mma per ks, ks 0..2 only.
//   dp4a:   accLo[8][4] (lo, kc 0..7) + accHd[8][4] (hi, kc 6..7);
//           rows wid+8i (broadcast A), cols lane+32j.
// 4-stage cp.async ring, prefetch distance 2, one __syncthreads per iter.
// ---------------------------------------------------------------------------
__global__ void __launch_bounds__(256, 1)
gemm_s8_kernel(const float* __restrict__ bias, float* __restrict__ out) {
    extern __shared__ char smem[];
    const uint32_t sb = smem_u32(smem);
    const int tid = threadIdx.x;
    const int lane = tid & 31;
    const int wid = tid >> 5;
    const int wm = wid >> 2;           // 0..1
    const int wn = wid & 3;            // 0..3
    const int m0 = blockIdx.y * BM;
    const int n0 = blockIdx.x * BN;

    // --- cp.async mapping (8 x 16B chunks per thread = 32 KB/stage) ---
    const int arow = tid >> 2;
    const int acol = (tid & 3) * 2;
    const int8_t* gH = g_xh8 + (size_t)(m0 + arow) * K_DIM + acol * 16;
    const int8_t* gL = g_xl8 + (size_t)(m0 + arow) * K_DIM + acol * 16;
    const uint32_t aBase = (uint32_t)arow * BK;
    const uint32_t asw0 = aBase + (uint32_t)(((acol + 0) ^ (arow & 7)) << 4);
    const uint32_t asw1 = aBase + (uint32_t)(((acol + 1) ^ (arow & 7)) << 4);
    const int brow = tid >> 1;
    const int bcol = (tid & 1) * 4;
    const int8_t* gW = g_w8 + (size_t)(n0 + brow) * K_DIM + bcol * 16;
    const uint32_t bBase = B_OFF + (uint32_t)brow * BK;
    uint32_t bsw[4];
#pragma unroll
    for (int j = 0; j < 4; ++j)
        bsw[j] = bBase + (uint32_t)(((bcol + j) ^ (brow & 7)) << 4);

#define PREFETCH(it) do {                                                     \
    const int _k = (it) * BK;                                                 \
    const uint32_t _s = sb + (uint32_t)((it) & (NSTAGE - 1)) * STAGE_BYTES;   \
    CP16(_s + A_HI_OFF + asw0, gH + _k);                                      \
    CP16(_s + A_HI_OFF + asw1, gH + _k + 16);                                 \
    CP16(_s + A_LO_OFF + asw0, gL + _k);                                      \
    CP16(_s + A_LO_OFF + asw1, gL + _k + 16);                                 \
    CP16(_s + bsw[0], gW + _k);                                               \
    CP16(_s + bsw[1], gW + _k + 16);                                          \
    CP16(_s + bsw[2], gW + _k + 32);                                          \
    CP16(_s + bsw[3], gW + _k + 48);                                          \
} while (0)

    // --- hi-path ldmatrix lane addressing ---
    const int ag = lane >> 3;
    const int aRow0 = wm * 32 + ((ag & 1) << 3) + (lane & 7);
    const int agc = ag >> 1;
    const int bRow = wn * 32 + lane;
    const uint32_t bRowOff = B_OFF + (uint32_t)bRow * BK;
    const int bRowSw = bRow & 7;

    int accH[2][4][4];
#pragma unroll
    for (int mt = 0; mt < 2; ++mt)
#pragma unroll
        for (int nt = 0; nt < 4; ++nt)
#pragma unroll
            for (int i = 0; i < 4; ++i) accH[mt][nt][i] = 0;

    // --- dp4a-path setup ---
    int accLo[8][4], accHd[8][4];
#pragma unroll
    for (int i = 0; i < 8; ++i)
#pragma unroll
        for (int j = 0; j < 4; ++j) { accLo[i][j] = 0; accHd[i][j] = 0; }
    const uint32_t loASw = (uint32_t)(wid & 7);             // warp-uniform
    uint32_t loBOff[4];
#pragma unroll
    for (int j = 0; j < 4; ++j)
        loBOff[j] = B_OFF + (uint32_t)(lane + 32 * j) * BK;
    const uint32_t loBSw = (uint32_t)(lane & 7);

// 4 rows (I0..I0+3) x 4 cols x 4 dp4a = 64 dp4a
#define DP_CHUNK(ACC, BASE, KC, I0, BW) do {                                  \
    _Pragma("unroll")                                                         \
    for (int _i = (I0); _i < (I0) + 4; ++_i) {                                \
        const uint4 _aw = *reinterpret_cast<const uint4*>(                    \
            smem + So + (BASE) + (uint32_t)(wid + 8 * _i) * BK +              \
            (((uint32_t)(KC) ^ loASw) << 4));                                 \
        _Pragma("unroll")                                                     \
        for (int _j = 0; _j < 4; ++_j) {                                      \
            int _a = ACC[_i][_j];                                             \
            _a = __dp4a((int)_aw.x, (int)(BW)[_j].x, _a);                     \
            _a = __dp4a((int)_aw.y, (int)(BW)[_j].y, _a);                     \
            _a = __dp4a((int)_aw.z, (int)(BW)[_j].z, _a);                     \
            _a = __dp4a((int)_aw.w, (int)(BW)[_j].w, _a);                     \
            ACC[_i][_j] = _a;                                                 \
        }                                                                     \
    }                                                                         \
} while (0)

#define LOAD_BW(BW, KC) do {                                                  \
    _Pragma("unroll")                                                         \
    for (int _j = 0; _j < 4; ++_j)                                            \
        (BW)[_j] = *reinterpret_cast<const uint4*>(                           \
            smem + So + loBOff[_j] + (((uint32_t)(KC) ^ loBSw) << 4));        \
} while (0)

    // --- prologue: fill 2 stages (prefetch distance 2) ---
    PREFETCH(0); CP_COMMIT();
    PREFETCH(1); CP_COMMIT();

    for (int it = 0; it < NKT; ++it) {
        CP_WAIT1();
        __syncthreads();
        if (it + 2 < NKT) { PREFETCH(it + 2); }
        CP_COMMIT();

        const uint32_t So = (uint32_t)(it & (NSTAGE - 1)) * STAGE_BYTES;
        const uint32_t S = sb + So;

        // ---- ks 0..2: hi on tensor, lo on dp4a, interleaved [2 mma|64 dp4a]
#pragma unroll
        for (int ks = 0; ks < 3; ++ks) {
            uint32_t b0[4], b1[4];
            {
                uint32_t a0 = S + bRowOff + (uint32_t)(((ks * 2)     ^ bRowSw) << 4);
                uint32_t a1 = S + bRowOff + (uint32_t)(((ks * 2 + 1) ^ bRowSw) << 4);
                LDSM4(b0[0], b0[1], b0[2], b0[3], a0);
                LDSM4(b1[0], b1[1], b1[2], b1[3], a1);
            }
            uint32_t ah[2][4];
#pragma unroll
            for (int mt = 0; mt < 2; ++mt) {
                const int rA = aRow0 + mt * 16;
                const int cA = ks * 2 + agc;
                const uint32_t off = (uint32_t)rA * BK +
                                     (uint32_t)((cA ^ (rA & 7)) << 4);
                LDSM4(ah[mt][0], ah[mt][1], ah[mt][2], ah[mt][3],
                      S + A_HI_OFF + off);
            }

            uint4 bwA[4];
            LOAD_BW(bwA, ks * 2);
            mma_s8(accH[0][0], ah[0], b0[0], b1[0]);
            mma_s8(accH[0][1], ah[0], b0[1], b1[1]);
            DP_CHUNK(accLo, A_LO_OFF, ks * 2, 0, bwA);
            mma_s8(accH[0][2], ah[0], b0[2], b1[2]);
            mma_s8(accH[0][3], ah[0], b0[3], b1[3]);
            DP_CHUNK(accLo, A_LO_OFF, ks * 2, 4, bwA);

            uint4 bwB[4];
            LOAD_BW(bwB, ks * 2 + 1);
            mma_s8(accH[1][0], ah[1], b0[0], b1[0]);
            mma_s8(accH[1][1], ah[1], b0[1], b1[1]);
            DP_CHUNK(accLo, A_LO_OFF, ks * 2 + 1, 0, bwB);
            mma_s8(accH[1][2], ah[1], b0[2], b1[2]);
            mma_s8(accH[1][3], ah[1], b0[3], b1[3]);
            DP_CHUNK(accLo, A_LO_OFF, ks * 2 + 1, 4, bwB);
        }

        // ---- ks 3 (kc 6,7): lo AND hi both on dp4a ----
#pragma unroll
        for (int h = 0; h < 2; ++h) {
            const int kc = 6 + h;
            uint4 bw[4];
            LOAD_BW(bw, kc);
            DP_CHUNK(accLo, A_LO_OFF, kc, 0, bw);
            DP_CHUNK(accHd, A_HI_OFF, kc, 0, bw);
            DP_CHUNK(accLo, A_LO_OFF, kc, 4, bw);
            DP_CHUNK(accHd, A_HI_OFF, kc, 4, bw);
        }
    }

    // --- stage dp4a accumulators to smem: lo at [0,32K), hiK3 at [32K,64K) ---
    __syncthreads();           // all mainloop smem reads done before reuse
    int* loS = reinterpret_cast<int*>(smem);
    int* hdS = reinterpret_cast<int*>(smem + 32768);
#pragma unroll
    for (int i = 0; i < 8; ++i)
#pragma unroll
        for (int j = 0; j < 4; ++j) {
            loS[(wid + 8 * i) * BN + lane + 32 * j] = accLo[i][j];
            hdS[(wid + 8 * i) * BN + lane + 32 * j] = accHd[i][j];
        }
    __syncthreads();

    // --- epilogue: combine, scale, bias, store fp32 ---
#pragma unroll
    for (int mt = 0; mt < 2; ++mt) {
        const int rl = wm * 32 + mt * 16 + (lane >> 2);
        const int r0 = m0 + rl;
        const float s0 = g_scale[r0];
        const float s1 = g_scale[r0 + 8];
#pragma unroll
        for (int nt = 0; nt < 4; ++nt) {
            const int cl = wn * 32 + nt * 8 + 2 * (lane & 3);
            const int col = n0 + cl;
            const float bv0 = __ldg(bias + col);
            const float bv1 = __ldg(bias + col + 1);
            const int* h = accH[mt][nt];
            const int i00 = rl * BN + cl, i01 = i00 + 1;
            const int i10 = (rl + 8) * BN + cl, i11 = i10 + 1;
            float2 o0, o1;
            o0.x = s0 * (float)(256 * (h[0] + hdS[i00]) + loS[i00]) + bv0;
            o0.y = s0 * (float)(256 * (h[1] + hdS[i01]) + loS[i01]) + bv1;
            o1.x = s1 * (float)(256 * (h[2] + hdS[i10]) + loS[i10]) + bv0;
            o1.y = s1 * (float)(256 * (h[3] + hdS[i11]) + loS[i11]) + bv1;
            *reinterpret_cast<float2*>(out + (size_t)r0 * N_DIM + col) = o0;
            *reinterpret_cast<float2*>(out + (size_t)(r0 + 8) * N_DIM + col) = o1;
        }
    }
#undef PREFETCH
#undef DP_CHUNK
#undef LOAD_BW
}

// ---------------------------------------------------------------------------
// Launch
// ---------------------------------------------------------------------------
extern "C" void kernel_launch(void* const* d_in, const int* in_sizes, int n_in,
                              void* d_out, int out_size) {
    const float* x    = (const float*)d_in[0];
    const float* w    = (const float*)d_in[1];
    const float* bias = (const float*)d_in[2];
    float* out = (float*)d_out;

    quant_all_kernel<<<M_DIM + (N_DIM * K_DIM / 4) / 256, 256>>>(x, w);

    cudaFuncSetAttribute(gemm_s8_kernel,
                         cudaFuncAttributeMaxDynamicSharedMemorySize, SMEM_TOTAL);
    dim3 grid(N_DIM / BN, M_DIM / BM);   // (32, 128): n fastest -> W L2-resident
    gemm_s8_kernel<<<grid, 256, SMEM_TOTAL>>>(bias, out);
}

// round 8
// speedup vs baseline: 1.6954x; 1.1824x over previous
#include <cuda_runtime.h>
#include <cuda_bf16.h>
#include <cstdint>

// ============================================================================
// TernaryLinear: out[8192,4096] = x[8192,4096] @ W[4096,4096]^T + bias
//
// R8: R7's balanced split (tensor: hi ks0-2; dp4a: lo all + hi ks3) with
// R4's coarse phase separation and SMALL per-warp tiles so regs stay < 128.
// 512 thr / 16 warps (4 per SMSP): mma warp tile 16x32 (accH 16 regs),
// dp4a 4 rows x 128 cols (accLo+accHd 32 regs). No spills, deep warp pool.
// out = s*(256*(hi_mma+hi_dp) + lo) + bias, all-int accumulation (exact).
// ============================================================================

#define M_DIM 8192
#define N_DIM 4096
#define K_DIM 4096
#define BM 64
#define BN 128
#define BK 128                     // int8 elems per K tile (128 B/row)
#define NKT (K_DIM / BK)           // 32
#define NSTAGE 4
#define A_HI_OFF 0
#define A_LO_OFF 8192
#define B_OFF    16384
#define STAGE_BYTES 32768          // A_hi 8K + A_lo 8K + B 16K
#define SMEM_TOTAL (NSTAGE * STAGE_BYTES)   // 128 KB

// Static device scratch (sanctioned workaround for no-alloc rule)
__device__ __align__(128) int8_t g_xh8[(size_t)M_DIM * K_DIM];
__device__ __align__(128) int8_t g_xl8[(size_t)M_DIM * K_DIM];
__device__ __align__(128) int8_t g_w8 [(size_t)N_DIM * K_DIM];
__device__ __align__(128) float  g_scale[M_DIM];

// ---------------------------------------------------------------------------
// PTX helpers
// ---------------------------------------------------------------------------
__device__ __forceinline__ uint32_t smem_u32(const void* p) {
    uint32_t a;
    asm("{ .reg .u64 t; cvta.to.shared.u64 t, %1; cvt.u32.u64 %0, t; }"
        : "=r"(a) : "l"(p));
    return a;
}

#define CP16(dst, src) \
    asm volatile("cp.async.cg.shared.global [%0], [%1], 16;" \
                 :: "r"((uint32_t)(dst)), "l"(src) : "memory")
#define CP_COMMIT() asm volatile("cp.async.commit_group;" ::: "memory")
#define CP_WAIT1()  asm volatile("cp.async.wait_group 1;" ::: "memory")

#define LDSM4(r0, r1, r2, r3, addr) \
    asm volatile("ldmatrix.sync.aligned.m8n8.x4.shared.b16 {%0,%1,%2,%3}, [%4];" \
                 : "=r"(r0), "=r"(r1), "=r"(r2), "=r"(r3) : "r"(addr))

__device__ __forceinline__ void mma_s8(int c[4], const uint32_t a[4],
                                       uint32_t b0, uint32_t b1) {
    asm volatile(
        "mma.sync.aligned.m16n8k32.row.col.s32.s8.s8.s32 "
        "{%0,%1,%2,%3}, {%4,%5,%6,%7}, {%8,%9}, {%0,%1,%2,%3};"
        : "+r"(c[0]), "+r"(c[1]), "+r"(c[2]), "+r"(c[3])
        : "r"(a[0]), "r"(a[1]), "r"(a[2]), "r"(a[3]), "r"(b0), "r"(b1));
}

// ---------------------------------------------------------------------------
// Merged pre-pass: blocks [0,8192) quantize x rows; [8192, 24576) convert W.
// ---------------------------------------------------------------------------
__global__ void __launch_bounds__(256) quant_all_kernel(const float* __restrict__ x,
                                                        const float* __restrict__ w) {
    const int t = threadIdx.x;
    if (blockIdx.x < M_DIM) {
        const int row = blockIdx.x;
        const float4* xr = reinterpret_cast<const float4*>(x + (size_t)row * K_DIM);
        float4 v[4];
        float amax = 0.f;
#pragma unroll
        for (int p = 0; p < 4; ++p) {
            v[p] = xr[p * 256 + t];
            amax = fmaxf(amax, fmaxf(fmaxf(fabsf(v[p].x), fabsf(v[p].y)),
                                     fmaxf(fabsf(v[p].z), fabsf(v[p].w))));
        }
#pragma unroll
        for (int o = 16; o; o >>= 1)
            amax = fmaxf(amax, __shfl_xor_sync(0xFFFFFFFFu, amax, o));

        __shared__ float smax[8];
        if ((t & 31) == 0) smax[t >> 5] = amax;
        __syncthreads();
        float bmax = fmaxf(fmaxf(fmaxf(smax[0], smax[1]), fmaxf(smax[2], smax[3])),
                           fmaxf(fmaxf(smax[4], smax[5]), fmaxf(smax[6], smax[7])));

        const float inv = (bmax > 0.f) ? (32639.f / bmax) : 0.f;
        if (t == 0) g_scale[row] = (bmax > 0.f) ? (bmax / 32639.f) : 0.f;

        char4* hp = reinterpret_cast<char4*>(g_xh8 + (size_t)row * K_DIM);
        char4* lp = reinterpret_cast<char4*>(g_xl8 + (size_t)row * K_DIM);
#pragma unroll
        for (int p = 0; p < 4; ++p) {
            int q0 = __float2int_rn(v[p].x * inv);
            int q1 = __float2int_rn(v[p].y * inv);
            int q2 = __float2int_rn(v[p].z * inv);
            int q3 = __float2int_rn(v[p].w * inv);
            int h0 = (q0 + 128) >> 8, h1 = (q1 + 128) >> 8;
            int h2 = (q2 + 128) >> 8, h3 = (q3 + 128) >> 8;
            char4 hc = make_char4((char)h0, (char)h1, (char)h2, (char)h3);
            char4 lc = make_char4((char)(q0 - (h0 << 8)), (char)(q1 - (h1 << 8)),
                                  (char)(q2 - (h2 << 8)), (char)(q3 - (h3 << 8)));
            hp[p * 256 + t] = hc;
            lp[p * 256 + t] = lc;
        }
    } else {
        size_t i = (size_t)(blockIdx.x - M_DIM) * 256 + t;   // float4 index
        float4 v = reinterpret_cast<const float4*>(w)[i];
        char4 c = make_char4((char)__float2int_rn(v.x), (char)__float2int_rn(v.y),
                             (char)__float2int_rn(v.z), (char)__float2int_rn(v.w));
        reinterpret_cast<char4*>(g_w8)[i] = c;
    }
}

// ---------------------------------------------------------------------------
// Main GEMM. CTA 64x128, 512 thr = 16 warps.
//   mma part: warps 4m x 4n, warp tile 16x32, ks 0..2 -> 12 mma/iter.
//   dp4a part: warp w owns rows w*4..w*4+3, lane owns cols lane+32j;
//              lo (kc 0..7) + hi (kc 6..7) -> 640 dp4a/iter.
// Phase: warps (wid>>2)&1==0 run mma->dp4a, ==1 run dp4a->mma, so every
// SMSP always feeds both pipes. 4-stage cp.async ring, distance 2.
// ---------------------------------------------------------------------------
__global__ void __launch_bounds__(512, 1)
gemm_s8_kernel(const float* __restrict__ bias, float* __restrict__ out) {
    extern __shared__ char smem[];
    const uint32_t sb = smem_u32(smem);
    const int tid = threadIdx.x;
    const int lane = tid & 31;
    const int wid = tid >> 5;
    const int wm = wid >> 2;           // 0..3 (16-row tiles)
    const int wn = wid & 3;            // 0..3 (32-col tiles)
    const int m0 = blockIdx.y * BM;
    const int n0 = blockIdx.x * BN;

    // --- cp.async mapping: 4 x 16B chunks per thread (32 KB / 512 thr) ---
    // A (hi & lo): thread t -> row t>>3 (0..63), chunk t&7; one chunk each.
    const int arow = tid >> 3;
    const int acol = tid & 7;
    const int8_t* gH = g_xh8 + (size_t)(m0 + arow) * K_DIM + acol * 16;
    const int8_t* gL = g_xl8 + (size_t)(m0 + arow) * K_DIM + acol * 16;
    const uint32_t asw = (uint32_t)arow * BK +
                         (uint32_t)((acol ^ (arow & 7)) << 4);
    // B: thread t -> row t>>2 (0..127), chunks (t&3)*2 + {0,1}
    const int brow = tid >> 2;
    const int bcol = (tid & 3) * 2;
    const int8_t* gW = g_w8 + (size_t)(n0 + brow) * K_DIM + bcol * 16;
    const uint32_t bsw0 = B_OFF + (uint32_t)brow * BK +
                          (uint32_t)(((bcol + 0) ^ (brow & 7)) << 4);
    const uint32_t bsw1 = B_OFF + (uint32_t)brow * BK +
                          (uint32_t)(((bcol + 1) ^ (brow & 7)) << 4);

#define PREFETCH(it) do {                                                     \
    const int _k = (it) * BK;                                                 \
    const uint32_t _s = sb + (uint32_t)((it) & (NSTAGE - 1)) * STAGE_BYTES;   \
    CP16(_s + A_HI_OFF + asw, gH + _k);                                       \
    CP16(_s + A_LO_OFF + asw, gL + _k);                                       \
    CP16(_s + bsw0, gW + _k);                                                 \
    CP16(_s + bsw1, gW + _k + 16);                                            \
} while (0)

    // --- mma lane addressing (16x32 warp tile) ---
    const int ag = lane >> 3;                               // 0..3
    const int aRow = wm * 16 + ((ag & 1) << 3) + (lane & 7);
    const int agc = ag >> 1;                                // k-chunk half
    const int bRow = wn * 32 + lane;
    const uint32_t bRowOff = B_OFF + (uint32_t)bRow * BK;
    const int bRowSw = bRow & 7;

    int accH[4][4];
#pragma unroll
    for (int nt = 0; nt < 4; ++nt)
#pragma unroll
        for (int i = 0; i < 4; ++i) accH[nt][i] = 0;

    // --- dp4a addressing: rows w*4+i, cols lane+32j ---
    int accLo[4][4], accHd[4][4];
#pragma unroll
    for (int i = 0; i < 4; ++i)
#pragma unroll
        for (int j = 0; j < 4; ++j) { accLo[i][j] = 0; accHd[i][j] = 0; }
    uint32_t dBOff[4];
#pragma unroll
    for (int j = 0; j < 4; ++j)
        dBOff[j] = B_OFF + (uint32_t)(lane + 32 * j) * BK;
    const uint32_t dBSw = (uint32_t)(lane & 7);
    const int dRow0 = wid * 4;                              // first dp4a row

    // --- prologue: fill 2 stages (prefetch distance 2) ---
    PREFETCH(0); CP_COMMIT();
    PREFETCH(1); CP_COMMIT();

    for (int it = 0; it < NKT; ++it) {
        CP_WAIT1();
        __syncthreads();
        if (it + 2 < NKT) { PREFETCH(it + 2); }
        CP_COMMIT();

        const uint32_t So = (uint32_t)(it & (NSTAGE - 1)) * STAGE_BYTES;
        const uint32_t S = sb + So;

        auto mma_part = [&]() {
#pragma unroll
            for (int ks = 0; ks < 3; ++ks) {
                uint32_t b0[4], b1[4];
                uint32_t a0 = S + bRowOff + (uint32_t)(((ks * 2)     ^ bRowSw) << 4);
                uint32_t a1 = S + bRowOff + (uint32_t)(((ks * 2 + 1) ^ bRowSw) << 4);
                LDSM4(b0[0], b0[1], b0[2], b0[3], a0);
                LDSM4(b1[0], b1[1], b1[2], b1[3], a1);
                uint32_t ah[4];
                {
                    const int cA = ks * 2 + agc;
                    const uint32_t off = (uint32_t)aRow * BK +
                                         (uint32_t)((cA ^ (aRow & 7)) << 4);
                    LDSM4(ah[0], ah[1], ah[2], ah[3], S + A_HI_OFF + off);
                }
#pragma unroll
                for (int nt = 0; nt < 4; ++nt)
                    mma_s8(accH[nt], ah, b0[nt], b1[nt]);
            }
        };

        auto dp_part = [&]() {
#pragma unroll
            for (int kc = 0; kc < 8; ++kc) {
                uint4 bw[4];
#pragma unroll
                for (int j = 0; j < 4; ++j)
                    bw[j] = *reinterpret_cast<const uint4*>(
                        smem + So + dBOff[j] + (((uint32_t)kc ^ dBSw) << 4));
#pragma unroll
                for (int i = 0; i < 4; ++i) {
                    const int rr = dRow0 + i;
                    const uint4 aw = *reinterpret_cast<const uint4*>(
                        smem + So + A_LO_OFF + (uint32_t)rr * BK +
                        (((uint32_t)kc ^ (uint32_t)(rr & 7)) << 4));
#pragma unroll
                    for (int j = 0; j < 4; ++j) {
                        int a = accLo[i][j];
                        a = __dp4a((int)aw.x, (int)bw[j].x, a);
                        a = __dp4a((int)aw.y, (int)bw[j].y, a);
                        a = __dp4a((int)aw.z, (int)bw[j].z, a);
                        a = __dp4a((int)aw.w, (int)bw[j].w, a);
                        accLo[i][j] = a;
                    }
                }
                if (kc >= 6) {   // hi pass ks=3 on dp4a (reuses bw)
#pragma unroll
                    for (int i = 0; i < 4; ++i) {
                        const int rr = dRow0 + i;
                        const uint4 aw = *reinterpret_cast<const uint4*>(
                            smem + So + A_HI_OFF + (uint32_t)rr * BK +
                            (((uint32_t)kc ^ (uint32_t)(rr & 7)) << 4));
#pragma unroll
                        for (int j = 0; j < 4; ++j) {
                            int a = accHd[i][j];
                            a = __dp4a((int)aw.x, (int)bw[j].x, a);
                            a = __dp4a((int)aw.y, (int)bw[j].y, a);
                            a = __dp4a((int)aw.z, (int)bw[j].z, a);
                            a = __dp4a((int)aw.w, (int)bw[j].w, a);
                            accHd[i][j] = a;
                        }
                    }
                }
            }
        };

        // Coarse phase stagger: each SMSP hosts warps {s, s+4, s+8, s+12};
        // (wid>>2)&1 alternates within that set -> 2 warps per pipe per SMSP.
        if (((wid >> 2) & 1) == 0) { mma_part(); dp_part(); }
        else                       { dp_part(); mma_part(); }
    }

    // --- stage dp4a accumulators: lo at [0,32K), hiK3 at [32K,64K) ---
    __syncthreads();           // all mainloop smem reads done before reuse
    int* loS = reinterpret_cast<int*>(smem);
    int* hdS = reinterpret_cast<int*>(smem + 32768);
#pragma unroll
    for (int i = 0; i < 4; ++i)
#pragma unroll
        for (int j = 0; j < 4; ++j) {
            loS[(dRow0 + i) * BN + lane + 32 * j] = accLo[i][j];
            hdS[(dRow0 + i) * BN + lane + 32 * j] = accHd[i][j];
        }
    __syncthreads();

    // --- epilogue: combine, scale, bias, store fp32 ---
    {
        const int rl = wm * 16 + (lane >> 2);
        const int r0 = m0 + rl;
        const float s0 = g_scale[r0];
        const float s1 = g_scale[r0 + 8];
#pragma unroll
        for (int nt = 0; nt < 4; ++nt) {
            const int cl = wn * 32 + nt * 8 + 2 * (lane & 3);
            const int col = n0 + cl;
            const float bv0 = __ldg(bias + col);
            const float bv1 = __ldg(bias + col + 1);
            const int* h = accH[nt];
            const int i00 = rl * BN + cl, i01 = i00 + 1;
            const int i10 = (rl + 8) * BN + cl, i11 = i10 + 1;
            float2 o0, o1;
            o0.x = s0 * (float)(256 * (h[0] + hdS[i00]) + loS[i00]) + bv0;
            o0.y = s0 * (float)(256 * (h[1] + hdS[i01]) + loS[i01]) + bv1;
            o1.x = s1 * (float)(256 * (h[2] + hdS[i10]) + loS[i10]) + bv0;
            o1.y = s1 * (float)(256 * (h[3] + hdS[i11]) + loS[i11]) + bv1;
            *reinterpret_cast<float2*>(out + (size_t)r0 * N_DIM + col) = o0;
            *reinterpret_cast<float2*>(out + (size_t)(r0 + 8) * N_DIM + col) = o1;
        }
    }
#undef PREFETCH
}

// ---------------------------------------------------------------------------
// Launch
// ---------------------------------------------------------------------------
extern "C" void kernel_launch(void* const* d_in, const int* in_sizes, int n_in,
                              void* d_out, int out_size) {
    const float* x    = (const float*)d_in[0];
    const float* w    = (const float*)d_in[1];
    const float* bias = (const float*)d_in[2];
    float* out = (float*)d_out;

    quant_all_kernel<<<M_DIM + (N_DIM * K_DIM / 4) / 256, 256>>>(x, w);

    cudaFuncSetAttribute(gemm_s8_kernel,
                         cudaFuncAttributeMaxDynamicSharedMemorySize, SMEM_TOTAL);
    dim3 grid(N_DIM / BN, M_DIM / BM);   // (32, 128): n fastest -> W L2-resident
    gemm_s8_kernel<<<grid, 512, SMEM_TOTAL>>>(bias, out);
}